// round 7
// baseline (speedup 1.0000x reference)
#include <cuda_runtime.h>
#include <cstdint>

#define NV 10000
#define NR 8
#define NC 64
#define NU 64

#define ROWS 64
#define NTHREADS 256
#define APAD 68                       // A fp32 row stride (conflict-free)

#define SA_FLOATS (ROWS * APAD)       // 4352 per buffer
#define SB_FLOATS 4096                // paired tf32 B per buffer (16KB)
#define SMEM_BYTES ((2*SA_FLOATS + 2*SB_FLOATS) * 4)   // 67584 -> 3 CTA/SM

// zero row for invalid (-1) gather slots
__device__ __align__(16) float g_zero[64] = {};

// ---------------- helpers ----------------
__device__ __forceinline__ unsigned cvta_smem(const void* p) {
    unsigned r;
    asm("{ .reg .u64 t; cvta.to.shared.u64 t, %1; cvt.u32.u64 %0, t; }"
        : "=r"(r) : "l"(p));
    return r;
}
__device__ __forceinline__ void cpasync16(unsigned dst, const void* src) {
    asm volatile("cp.async.cg.shared.global [%0], [%1], 16;" :: "r"(dst), "l"(src));
}
#define CP_COMMIT() asm volatile("cp.async.commit_group;" ::: "memory")
#define CP_WAIT(n)  asm volatile("cp.async.wait_group %0;" :: "n"(n) : "memory")

__device__ __forceinline__ unsigned cvt_tf32(float f) {
    unsigned t;
    asm("cvt.rna.tf32.f32 %0, %1;" : "=r"(t) : "f"(f));
    return t;
}
__device__ __forceinline__ void ldsm_x4(unsigned addr, unsigned& r0, unsigned& r1,
                                        unsigned& r2, unsigned& r3) {
    asm volatile("ldmatrix.sync.aligned.m8n8.x4.shared.b16 {%0,%1,%2,%3}, [%4];"
                 : "=r"(r0), "=r"(r1), "=r"(r2), "=r"(r3) : "r"(addr));
}
__device__ __forceinline__ void mma_tf32(float& d0, float& d1, float& d2, float& d3,
                                         unsigned a0, unsigned a1, unsigned a2, unsigned a3,
                                         unsigned b0, unsigned b1) {
    asm volatile("mma.sync.aligned.m16n8k8.row.col.f32.tf32.tf32.f32 "
                 "{%0,%1,%2,%3}, {%4,%5,%6,%7}, {%8,%9}, {%0,%1,%2,%3};"
                 : "+f"(d0), "+f"(d1), "+f"(d2), "+f"(d3)
                 : "r"(a0), "r"(a1), "r"(a2), "r"(a3), "r"(b0), "r"(b1));
}

__global__ void __launch_bounds__(NTHREADS, 3)
graphconv_mma(const float* __restrict__ nodes,
              const int*   __restrict__ mapping,
              const float* __restrict__ kern,
              const float* __restrict__ bias,
              float*       __restrict__ out)
{
    extern __shared__ float smem[];
    float* sA = smem;                       // [2][ROWS][APAD]
    float* sB = smem + 2 * SA_FLOATS;       // [2][2048] float2 (paired tf32)
    const unsigned sA_u = cvta_smem(sA);

    const int tid  = threadIdx.x;
    const int row0 = blockIdx.x * ROWS;

    const int wid = tid >> 5;
    const int l   = tid & 31;
    const int mg  = wid & 1;                // m-group: rows mg*32 .. mg*32+31
    const int ng  = wid >> 1;               // n-group: u  ng*16 .. ng*16+15

    // ---- gather roles: 4 lanes per row, 4 x 16B chunks each ----
    const int gm   = tid >> 2;              // local row 0..63
    const int gl   = tid & 3;
    const int grow = row0 + gm;
    const int bV   = (grow / NV) * NV;

    // ---- A fragment ldmatrix lane address (fixed part) ----
    const unsigned a_lane_rel =
        (unsigned)(((mg * 32 + (l & 15)) * APAD + ((l >> 4) << 2)) * 4);

    // ---- B fragment float2-index (fixed part): conflict-free LDS.64 ----
    const int b_lane_rel = ng * 64 + (l >> 2) * 4 + (l & 3);

    float d[2][2][4];
#pragma unroll
    for (int mt = 0; mt < 2; ++mt)
#pragma unroll
        for (int nt = 0; nt < 2; ++nt)
#pragma unroll
            for (int q = 0; q < 4; ++q) d[mt][nt][q] = 0.f;

    // ---- prologue: region 0 A (cp.async) + B (LDG->cvt->STS paired tf32) ----
    int m_cur = __ldg(mapping + (size_t)grow * NR);
    {
        const float* src = (m_cur >= 0)
            ? nodes + ((size_t)(bV + m_cur) << 6) + gl * 16 : g_zero + gl * 16;
        unsigned dA = sA_u + (unsigned)((gm * APAD) * 4 + gl * 64);
#pragma unroll
        for (int j = 0; j < 4; ++j) cpasync16(dA + j * 16, src + j * 4);
        CP_COMMIT();

        uint2* Bn = (uint2*)sB;
#pragma unroll
        for (int i = 0; i < 8; ++i) {
            const int j  = tid + i * NTHREADS;   // float2 index 0..2047
            const int k0 = ((j >> 8) << 3) + (j & 3);
            const int u  = (j >> 2) & 63;
            uint2 t;
            t.x = cvt_tf32(__ldg(kern + k0 * NU + u));
            t.y = cvt_tf32(__ldg(kern + (k0 + 4) * NU + u));
            Bn[j] = t;
        }
    }
    int m_nxt = __ldg(mapping + (size_t)grow * NR + 1);

#pragma unroll 1
    for (int r = 0; r < NR; ++r) {
        const int buf = r & 1;

        // ---- stage region r+1 into the other buffer ----
        if (r < NR - 1) {
            const int nb = buf ^ 1;
            const float* src = (m_nxt >= 0)
                ? nodes + ((size_t)(bV + m_nxt) << 6) + gl * 16 : g_zero + gl * 16;
            unsigned dA = sA_u + (unsigned)((nb * SA_FLOATS + gm * APAD) * 4 + gl * 64);
#pragma unroll
            for (int j = 0; j < 4; ++j) cpasync16(dA + j * 16, src + j * 4);
            CP_COMMIT();

            const float* kg = kern + (size_t)(r + 1) * (NC * NU);
            uint2* Bn = (uint2*)(sB + nb * SB_FLOATS);
#pragma unroll
            for (int i = 0; i < 8; ++i) {
                const int j  = tid + i * NTHREADS;
                const int k0 = ((j >> 8) << 3) + (j & 3);
                const int u  = (j >> 2) & 63;
                uint2 t;
                t.x = cvt_tf32(__ldg(kg + k0 * NU + u));
                t.y = cvt_tf32(__ldg(kg + (k0 + 4) * NU + u));
                Bn[j] = t;
            }
            if (r < NR - 2) m_nxt = __ldg(mapping + (size_t)grow * NR + r + 2);
        }

        if (r < NR - 1) { CP_WAIT(1); } else { CP_WAIT(0); }
        __syncthreads();

        const unsigned aaddr0 = sA_u + (unsigned)(buf * SA_FLOATS * 4) + a_lane_rel;
        const uint2*   Bb     = (const uint2*)(sB + buf * SB_FLOATS) + b_lane_rel;

        // ---- 8 k-steps, register double-buffered fragments ----
        unsigned a[2][2][4];
        uint2    b[2][2];

#pragma unroll
        for (int mt = 0; mt < 2; ++mt) {
            ldsm_x4(aaddr0 + (unsigned)((mt * 16 * APAD) * 4),
                    a[0][mt][0], a[0][mt][1], a[0][mt][2], a[0][mt][3]);
#pragma unroll
            for (int q = 0; q < 4; ++q)
                a[0][mt][q] = cvt_tf32(__uint_as_float(a[0][mt][q]));
        }
#pragma unroll
        for (int nt = 0; nt < 2; ++nt) b[0][nt] = Bb[nt * 32];

#pragma unroll
        for (int ks = 0; ks < 8; ++ks) {
            const int cur = ks & 1, nxt = cur ^ 1;
            if (ks < 7) {
                const int k1 = (ks + 1) * 8;
#pragma unroll
                for (int mt = 0; mt < 2; ++mt) {
                    ldsm_x4(aaddr0 + (unsigned)((mt * 16 * APAD + k1) * 4),
                            a[nxt][mt][0], a[nxt][mt][1], a[nxt][mt][2], a[nxt][mt][3]);
#pragma unroll
                    for (int q = 0; q < 4; ++q)
                        a[nxt][mt][q] = cvt_tf32(__uint_as_float(a[nxt][mt][q]));
                }
#pragma unroll
                for (int nt = 0; nt < 2; ++nt)
                    b[nxt][nt] = Bb[(ks + 1) * 256 + nt * 32];
            }
#pragma unroll
            for (int mt = 0; mt < 2; ++mt)
#pragma unroll
                for (int nt = 0; nt < 2; ++nt)
                    mma_tf32(d[mt][nt][0], d[mt][nt][1], d[mt][nt][2], d[mt][nt][3],
                             a[cur][mt][0], a[cur][mt][1], a[cur][mt][2], a[cur][mt][3],
                             b[cur][nt].x, b[cur][nt].y);
        }
        __syncthreads();   // all warps done reading buf before refill
    }

    // ---- epilogue: bias + relu + STG.64 straight from fragments ----
#pragma unroll
    for (int nt = 0; nt < 2; ++nt) {
        const int u0 = ng * 16 + nt * 8 + 2 * (l & 3);
        float2 bv = *(const float2*)(bias + u0);
#pragma unroll
        for (int mt = 0; mt < 2; ++mt) {
            const int rA = row0 + mg * 32 + mt * 16 + (l >> 2);
            float2 o0, o1;
            o0.x = fmaxf(d[mt][nt][0] + bv.x, 0.f);
            o0.y = fmaxf(d[mt][nt][1] + bv.y, 0.f);
            o1.x = fmaxf(d[mt][nt][2] + bv.x, 0.f);
            o1.y = fmaxf(d[mt][nt][3] + bv.y, 0.f);
            *(float2*)(out + (size_t)rA * NU + u0)       = o0;
            *(float2*)(out + (size_t)(rA + 8) * NU + u0) = o1;
        }
    }
}

extern "C" void kernel_launch(void* const* d_in, const int* in_sizes, int n_in,
                              void* d_out, int out_size) {
    (void)in_sizes; (void)n_in; (void)out_size;
    const float* nodes   = (const float*)d_in[0];
    const int*   mapping = (const int*)d_in[1];
    const float* kern    = (const float*)d_in[2];
    const float* bias    = (const float*)d_in[3];
    float*       out     = (float*)d_out;

    cudaFuncSetAttribute(graphconv_mma,
                         cudaFuncAttributeMaxDynamicSharedMemorySize, SMEM_BYTES);

    int grid = (16 * NV) / ROWS;   // 2500
    graphconv_mma<<<grid, NTHREADS, SMEM_BYTES>>>(nodes, mapping, kern, bias, out);
}